// round 1
// baseline (speedup 1.0000x reference)
#include <cuda_runtime.h>
#include <cuda_bf16.h>

// Problem shapes (fixed by setup_inputs)
#define B_      4
#define L_      8192
#define BLOCK_  128
#define NB_     (L_ / BLOCK_)          // 64
#define V_      32000
#define D_      1024
#define NT_     (L_ + NB_)             // 8256 new_tokens per batch row

// Output layout (flattened tuple, row-major, float32):
//   [0,              B*NT)                 new_tokens
//   [OFF_CE,         OFF_CE + B*NB*D)      cat_emb
//   [OFF_H,          OFF_H  + B*NB*V)      hist
#define OFF_CE  (B_ * NT_)                         // 33024
#define OFF_H   (OFF_CE + B_ * NB_ * D_)           // 295168

__global__ __launch_bounds__(256)
void chunk_agg_kernel(const int* __restrict__ tokens,
                      const float* __restrict__ catW,
                      float* __restrict__ out)
{
    const int bj  = blockIdx.x;          // 0 .. B*NB-1 (256)
    const int b   = bj >> 6;             // bj / NB
    const int j   = bj & 63;             // bj % NB
    const int tid = threadIdx.x;

    const int* __restrict__ blk = tokens + (size_t)b * L_ + (size_t)j * BLOCK_;
    const int t0 = blk[0];               // cat_dummy for this block

    // ---- 1) zero this block's private hist slice (32000 f32 = 8000 float4)
    float* __restrict__ hist = out + OFF_H + (size_t)bj * V_;
    float4* __restrict__ hist4 = reinterpret_cast<float4*>(hist);
    const float4 z4 = make_float4(0.f, 0.f, 0.f, 0.f);
    #pragma unroll 4
    for (int i = tid; i < V_ / 4; i += 256)
        hist4[i] = z4;

    // ---- 2) cat_emb row copy: 1024 f32 = 256 float4, one per thread
    {
        const float4* __restrict__ src =
            reinterpret_cast<const float4*>(catW + (size_t)t0 * D_);
        float4* __restrict__ dst =
            reinterpret_cast<float4*>(out + OFF_CE + (size_t)bj * D_);
        dst[tid] = src[tid];
    }

    // ---- 3) new_tokens: cat_dummy prefix + raw tokens (cast to f32)
    if (tid < BLOCK_)
        out[(size_t)b * NT_ + NB_ + (size_t)j * BLOCK_ + tid] = (float)blk[tid];
    if (tid == 0)
        out[(size_t)b * NT_ + j] = (float)t0;

    // ---- 4) histogram scatter into the zeroed private slice
    __syncthreads();
    if (tid < BLOCK_)
        atomicAdd(&hist[blk[tid]], 1.0f);
}

extern "C" void kernel_launch(void* const* d_in, const int* in_sizes, int n_in,
                              void* d_out, int out_size)
{
    const int*   tokens = (const int*)  d_in[0];   // [4, 8192] int32
    const float* catW   = (const float*)d_in[1];   // [32000, 1024] f32
    // d_in[2] (num_embed_W) is a dead lookup in the reference — unused.
    float* out = (float*)d_out;

    chunk_agg_kernel<<<B_ * NB_, 256>>>(tokens, catW, out);
}